// round 1
// baseline (speedup 1.0000x reference)
#include <cuda_runtime.h>

// IF (integrate-and-fire) scan:
//   x: (BT=256, C=64, H=56, W=56) fp32, viewed as (B=32, T=8, CHW=200704)
//   per neuron n=(b,chw): mem=0; for t: mem+=x[b,t,chw]; s=(mem>1); mem=s?0:mem; out[b,t,chw]=s
// Pure streaming: 205.5MB in + 205.5MB out. One thread owns 4 contiguous
// neurons (float4) across all 8 timesteps; loads are scan-independent so the
// compiler front-batches them for MLP=8.

#define T_STEPS 8
#define BATCH 32
#define CHW 200704              // 64*56*56
#define CHW4 (CHW / 4)          // 50176 float4 per timestep-slice
#define VTH 1.0f

__global__ void __launch_bounds__(256) if_scan_kernel(
    const float4* __restrict__ x, float4* __restrict__ out)
{
    const long long idx = (long long)blockIdx.x * blockDim.x + threadIdx.x;
    const long long total = (long long)BATCH * CHW4;   // 1,605,632
    if (idx >= total) return;

    const int b = (int)(idx / CHW4);
    const int p = (int)(idx % CHW4);
    const long long base = (long long)b * T_STEPS * CHW4 + p;

    // Front-batch all 8 loads (independent of scan state)
    float4 xt[T_STEPS];
#pragma unroll
    for (int t = 0; t < T_STEPS; t++)
        xt[t] = x[base + (long long)t * CHW4];

    float mx = 0.f, my = 0.f, mz = 0.f, mw = 0.f;
#pragma unroll
    for (int t = 0; t < T_STEPS; t++) {
        mx += xt[t].x; my += xt[t].y; mz += xt[t].z; mw += xt[t].w;
        float4 s;
        s.x = (mx > VTH) ? 1.0f : 0.0f;
        s.y = (my > VTH) ? 1.0f : 0.0f;
        s.z = (mz > VTH) ? 1.0f : 0.0f;
        s.w = (mw > VTH) ? 1.0f : 0.0f;
        // hard reset
        mx = (mx > VTH) ? 0.0f : mx;
        my = (my > VTH) ? 0.0f : my;
        mz = (mz > VTH) ? 0.0f : mz;
        mw = (mw > VTH) ? 0.0f : mw;
        out[base + (long long)t * CHW4] = s;
    }
}

extern "C" void kernel_launch(void* const* d_in, const int* in_sizes, int n_in,
                              void* d_out, int out_size)
{
    const float4* x = (const float4*)d_in[0];
    float4* out = (float4*)d_out;
    const long long total = (long long)BATCH * CHW4;
    const int threads = 256;
    const int blocks = (int)((total + threads - 1) / threads);
    if_scan_kernel<<<blocks, threads>>>(x, out);
}